// round 16
// baseline (speedup 1.0000x reference)
#include <cuda_runtime.h>
#include <cuda_fp16.h>
#include <stdint.h>
#include <math.h>

#define BB 4
#define CC 256
#define HWN 4096
#define QT 128
#define KT 64
#define NIT (HWN/KT)
#define SW128(x) ((x) ^ (((x) >> 3) & 0x70))

using f16 = __half;

// ---------------- scratch (device globals; no allocation allowed) ----------------
__device__ f16 g_hT[(size_t)BB*HWN*CC];     // groupnorm out, [n,c] fp16
__device__ f16 g_wT[4*CC*CC];               // WT[d,c] (q,k,v,p consecutive)
__device__ f16 g_q[(size_t)BB*HWN*CC];      // qT[n,d], pre-scaled by log2e/16
__device__ f16 g_k[(size_t)BB*HWN*CC];      // kT[n,d]
__device__ f16 g_v[(size_t)BB*CC*HWN];      // v[c,m]
__device__ f16 g_oT[(size_t)BB*HWN*CC];     // attention out, fp16

// ---------------- helpers ----------------
__device__ __forceinline__ uint32_t smem_u32(const void* p) {
    uint32_t a;
    asm("{ .reg .u64 t; cvta.to.shared.u64 t, %1; cvt.u32.u64 %0, t; }" : "=r"(a) : "l"(p));
    return a;
}
__device__ __forceinline__ uint32_t packh2(float lo, float hi) {
    uint32_t u;
    asm("cvt.rn.f16x2.f32 %0, %2, %1;" : "=r"(u) : "f"(lo), "f"(hi));
    return u;
}
__device__ __forceinline__ float ex2(float x) {
    float r;
    asm("ex2.approx.f32 %0, %1;" : "=f"(r) : "f"(x));
    return r;
}
__device__ __forceinline__ void cp_async16(uint32_t saddr, const void* g) {
    asm volatile("cp.async.cg.shared.global [%0], [%1], 16;" :: "r"(saddr), "l"(g) : "memory");
}
__device__ __forceinline__ void cp_commit() { asm volatile("cp.async.commit_group;" ::: "memory"); }
__device__ __forceinline__ void cp_wait1()  { asm volatile("cp.async.wait_group 1;" ::: "memory"); }
__device__ __forceinline__ void cp_wait0()  { asm volatile("cp.async.wait_group 0;" ::: "memory"); }

__device__ __forceinline__ void ldm_x4(uint32_t (&r)[4], uint32_t a) {
    asm volatile("ldmatrix.sync.aligned.m8n8.x4.shared.b16 {%0,%1,%2,%3}, [%4];"
        : "=r"(r[0]), "=r"(r[1]), "=r"(r[2]), "=r"(r[3]) : "r"(a));
}
__device__ __forceinline__ void mma16816(float (&d)[4], const uint32_t (&a)[4],
                                         uint32_t b0, uint32_t b1) {
    asm volatile(
        "mma.sync.aligned.m16n8k16.row.col.f32.f16.f16.f32 "
        "{%0,%1,%2,%3},{%4,%5,%6,%7},{%8,%9},{%0,%1,%2,%3};"
        : "+f"(d[0]), "+f"(d[1]), "+f"(d[2]), "+f"(d[3])
        : "r"(a[0]), "r"(a[1]), "r"(a[2]), "r"(a[3]), "r"(b0), "r"(b1));
}

// ---------------- GroupNorm (single gmem read via SMEM slab) ----------------
__global__ void __launch_bounds__(256, 1) gn_kernel(
    const float* __restrict__ x, const float* __restrict__ w, const float* __restrict__ b) {
    extern __shared__ float xs[];   // 8 * 4096 floats = 128KB
    int batch = blockIdx.x >> 5, g = blockIdx.x & 31;
    const float* xp = x + ((size_t)batch*CC + g*8) * HWN;
    int tid = threadIdx.x;
    float s = 0.f, ss = 0.f;
    for (int i = tid; i < 8*HWN; i += 256) {
        float v = xp[i];
        xs[i] = v;
        s += v; ss += v*v;
    }
    __shared__ float rs[256], rss[256];
    rs[tid] = s; rss[tid] = ss;
    __syncthreads();
    for (int st = 128; st > 0; st >>= 1) {
        if (tid < st) { rs[tid] += rs[tid+st]; rss[tid] += rss[tid+st]; }
        __syncthreads();
    }
    float mean = rs[0] * (1.f/32768.f);
    float var  = rss[0] * (1.f/32768.f) - mean*mean;
    float rstd = rsqrtf(var + 1e-5f);
    float ws[8], bs[8];
    #pragma unroll
    for (int c = 0; c < 8; c++) { ws[c] = w[g*8+c]*rstd; bs[c] = b[g*8+c]; }
    f16* oh = g_hT + (size_t)batch*HWN*CC + g*8;
    for (int n = tid; n < HWN; n += 256) {
        union { f16 v[8]; uint4 u; } hh;
        #pragma unroll
        for (int c = 0; c < 8; c++) {
            float v = (xs[c*HWN + n] - mean)*ws[c] + bs[c];
            hh.v[c] = __float2half(v);
        }
        *(uint4*)(oh + (size_t)n*CC) = hh.u;
    }
}

// ---------------- weight transpose: W[c,d] -> WT[d,c] fp16 ----------------
__global__ void wprep_kernel(const float* __restrict__ Wq, const float* __restrict__ Wk,
                             const float* __restrict__ Wv, const float* __restrict__ Wp) {
    const float* W = (blockIdx.y == 0) ? Wq : (blockIdx.y == 1) ? Wk : (blockIdx.y == 2) ? Wv : Wp;
    int d = blockIdx.x, c = threadIdx.x;
    g_wT[(size_t)blockIdx.y*CC*CC + (size_t)d*CC + c] = __float2half(W[(size_t)c*CC + d]);
}

// ---------------- fused QK: A (hT tile) resident, stream q,k weight B-tiles ----------------
// Both outputs are [n,d] -> coalesced stores. q pre-scaled by log2e/16.
__global__ void __launch_bounds__(256, 2) qk_kernel(
    const float* __restrict__ bq, const float* __restrict__ bk)
{
    extern __shared__ char smem[];
    const int tid = threadIdx.x;
    const int wid = tid >> 5, lane = tid & 31;
    const int warpM = wid & 3, warpN = wid >> 2;
    const int iBase = blockIdx.y * 128;      // n rows
    const int jBase = blockIdx.x * 128;      // d cols
    const int z = blockIdx.z;
    const f16* Ap = g_hT + (size_t)z*HWN*CC;

    const uint32_t sb = smem_u32(smem);
    const uint32_t BOFF = 65536;
    const float SCALE_Q = 0.0625f * 1.44269504088896f;

    #pragma unroll
    for (int q16 = 0; q16 < 16; q16++) {
        int idx = q16*256 + tid;
        int c = idx >> 10, r = (idx >> 3) & 127, b = idx & 7;
        cp_async16(sb + c*16384 + SW128(r*128 + b*16),
                   Ap + (size_t)(iBase + r)*CC + c*64 + b*8);
    }
    #define LOAD_B(m_, s_) do { \
        int o_ = (m_) >> 2, kc_ = (m_) & 3; \
        const f16* src = g_wT + (size_t)o_*CC*CC; \
        _Pragma("unroll") \
        for (int q4 = 0; q4 < 4; q4++) { \
            int idx = q4*256 + tid; \
            int r = (idx >> 3) & 127, b = idx & 7; \
            cp_async16(sb + BOFF + (s_)*16384 + SW128(r*128 + b*16), \
                       src + (size_t)(jBase + r)*CC + kc_*64 + b*8); \
        } \
    } while (0)

    LOAD_B(0, 0);
    cp_commit();

    const int aRowOff   = lane & 15;
    const int aChunkOff = (lane >> 4) & 1;
    const int bRowOff   = (((lane >> 4) & 1) << 3) + (lane & 7);
    const int bChunkOff = (lane >> 3) & 1;
    const int g = lane >> 2, t = lane & 3;

    float acc[2][8][4];

    for (int m = 0; m < 8; m++) {
        const int kc = m & 3, o = m >> 2;
        if (kc == 0) {
            #pragma unroll
            for (int a = 0; a < 2; a++)
                #pragma unroll
                for (int bq_ = 0; bq_ < 8; bq_++)
                    #pragma unroll
                    for (int cq = 0; cq < 4; cq++) acc[a][bq_][cq] = 0.f;
        }
        if (m > 0) __syncthreads();
        if (m + 1 < 8) { LOAD_B(m + 1, (m + 1) & 1); cp_commit(); cp_wait1(); }
        else           { cp_wait0(); }
        __syncthreads();

        const uint32_t ast = sb + kc*16384;
        const uint32_t bst = sb + BOFF + (m & 1)*16384;
        #pragma unroll
        for (int ks = 0; ks < 4; ks++) {
            uint32_t ah[2][4];
            #pragma unroll
            for (int mt = 0; mt < 2; mt++) {
                int row = warpM*32 + mt*16 + aRowOff;
                ldm_x4(ah[mt], ast + SW128((uint32_t)(row*128 + (2*ks + aChunkOff)*16)));
            }
            uint32_t bh[8][2];
            #pragma unroll
            for (int np = 0; np < 4; np++) {
                int row = warpN*64 + np*16 + bRowOff;
                uint32_t r4[4];
                ldm_x4(r4, bst + SW128((uint32_t)(row*128 + (2*ks + bChunkOff)*16)));
                bh[np*2][0] = r4[0]; bh[np*2][1] = r4[1];
                bh[np*2+1][0] = r4[2]; bh[np*2+1][1] = r4[3];
            }
            #pragma unroll
            for (int mt = 0; mt < 2; mt++)
                #pragma unroll
                for (int nt = 0; nt < 8; nt++)
                    mma16816(acc[mt][nt], ah[mt], bh[nt][0], bh[nt][1]);
        }

        if (kc == 3) {
            const float* bias = (o == 0) ? bq : bk;
            f16* qkp = ((o == 0) ? g_q : g_k) + (size_t)z*HWN*CC;
            const float sc = (o == 0) ? SCALE_Q : 1.0f;
            #pragma unroll
            for (int mt = 0; mt < 2; mt++) {
                int r0 = iBase + warpM*32 + mt*16 + g;
                int r1 = r0 + 8;
                #pragma unroll
                for (int nt = 0; nt < 8; nt++) {
                    int j = jBase + warpN*64 + nt*8 + 2*t;
                    float bj0 = bias[j], bj1 = bias[j+1];
                    *(uint32_t*)(qkp + (size_t)r0*CC + j) =
                        packh2((acc[mt][nt][0] + bj0)*sc, (acc[mt][nt][1] + bj1)*sc);
                    *(uint32_t*)(qkp + (size_t)r1*CC + j) =
                        packh2((acc[mt][nt][2] + bj0)*sc, (acc[mt][nt][3] + bj1)*sc);
                }
            }
        }
    }
    #undef LOAD_B
}

// ---------------- 1-term fp16 GEMM (NT), fp16 out + row bias — used for V ----------------
// D[i,j] = sum_k A[i,k]*B[j,k] + biasI[i].  A = weights (not batched), B batched.
__global__ void __launch_bounds__(256, 2) mma_gemm1h(
    const f16* __restrict__ A,
    const f16* __restrict__ B, size_t sB,
    int K,
    f16* __restrict__ outH, int ldo, size_t sO,
    const float* __restrict__ biasI)
{
    extern __shared__ char smem[];
    const int tid = threadIdx.x;
    const int wid = tid >> 5, lane = tid & 31;
    const int warpM = wid & 3, warpN = wid >> 2;
    const int iBase = blockIdx.y * 128;
    const int jBase = blockIdx.x * 128;
    const int z = blockIdx.z;
    B += (size_t)z * sB;

    const uint32_t sbase = smem_u32(smem);
    const int KC = K >> 6;

    #define LOAD_CHUNK1(kc, st_) do { \
        uint32_t stB = sbase + (st_)*32768; \
        int k0 = (kc) * 64; \
        _Pragma("unroll") \
        for (int qq = 0; qq < 8; qq++) { \
            int idx = qq*256 + tid; \
            int sub = idx >> 10; \
            int r = (idx >> 3) & 127; \
            int c = idx & 7; \
            const f16* gp = (sub == 0) ? A : B; \
            size_t rowoff = (sub == 0) ? ((size_t)(iBase + r) * K) : ((size_t)(jBase + r) * K); \
            uint32_t sa = stB + sub*16384 + SW128(r*128 + c*16); \
            cp_async16(sa, gp + rowoff + k0 + c*8); \
        } \
        cp_commit(); \
    } while (0)

    float acc[2][8][4];
    #pragma unroll
    for (int a = 0; a < 2; a++)
        #pragma unroll
        for (int bq_ = 0; bq_ < 8; bq_++)
            #pragma unroll
            for (int cq = 0; cq < 4; cq++) acc[a][bq_][cq] = 0.f;

    const int aRowOff   = lane & 15;
    const int aChunkOff = (lane >> 4) & 1;
    const int bRowOff   = (((lane >> 4) & 1) << 3) + (lane & 7);
    const int bChunkOff = (lane >> 3) & 1;

    LOAD_CHUNK1(0, 0);
    for (int kc = 0; kc < KC; kc++) {
        if (kc + 1 < KC) { LOAD_CHUNK1(kc + 1, (kc + 1) & 1); cp_wait1(); }
        else             { cp_wait0(); }
        __syncthreads();
        uint32_t st = sbase + (kc & 1) * 32768;
        #pragma unroll
        for (int ks = 0; ks < 4; ks++) {
            uint32_t ah[2][4];
            #pragma unroll
            for (int mt = 0; mt < 2; mt++) {
                int row = warpM*32 + mt*16 + aRowOff;
                ldm_x4(ah[mt], st + SW128((uint32_t)(row*128 + (2*ks + aChunkOff)*16)));
            }
            uint32_t bh[8][2];
            #pragma unroll
            for (int np = 0; np < 4; np++) {
                int row = warpN*64 + np*16 + bRowOff;
                uint32_t r4[4];
                ldm_x4(r4, st + 16384 + SW128((uint32_t)(row*128 + (2*ks + bChunkOff)*16)));
                bh[np*2][0] = r4[0]; bh[np*2][1] = r4[1];
                bh[np*2+1][0] = r4[2]; bh[np*2+1][1] = r4[3];
            }
            #pragma unroll
            for (int mt = 0; mt < 2; mt++)
                #pragma unroll
                for (int nt = 0; nt < 8; nt++)
                    mma16816(acc[mt][nt], ah[mt], bh[nt][0], bh[nt][1]);
        }
        __syncthreads();
    }
    #undef LOAD_CHUNK1

    const int g = lane >> 2, t = lane & 3;
    #pragma unroll
    for (int mt = 0; mt < 2; mt++) {
        int r0 = iBase + warpM*32 + mt*16 + g;
        int r1 = r0 + 8;
        float bi0 = biasI[r0];
        float bi1 = biasI[r1];
        #pragma unroll
        for (int nt = 0; nt < 8; nt++) {
            int j = jBase + warpN*64 + nt*8 + 2*t;
            f16* op = outH + (size_t)z*sO;
            *(uint32_t*)(op + (size_t)r0*ldo + j) = packh2(acc[mt][nt][0] + bi0, acc[mt][nt][1] + bi0);
            *(uint32_t*)(op + (size_t)r1*ldo + j) = packh2(acc[mt][nt][2] + bi1, acc[mt][nt][3] + bi1);
        }
    }
}

// ---------------- 1-term fp16 GEMM (NT), fp32 out + residual — final projection ----------------
__global__ void __launch_bounds__(256, 2) mma_gemm1f(
    const f16* __restrict__ A,
    const f16* __restrict__ B, size_t sB,
    int K,
    float* __restrict__ outF, int ldo, size_t sO,
    const float* __restrict__ biasI,
    const float* __restrict__ resid, size_t sR, float oscale)
{
    extern __shared__ char smem[];
    const int tid = threadIdx.x;
    const int wid = tid >> 5, lane = tid & 31;
    const int warpM = wid & 3, warpN = wid >> 2;
    const int iBase = blockIdx.y * 128;
    const int jBase = blockIdx.x * 128;
    const int z = blockIdx.z;
    B += (size_t)z * sB;

    const uint32_t sbase = smem_u32(smem);
    const int KC = K >> 6;

    #define LOAD_CHUNK1(kc, st_) do { \
        uint32_t stB = sbase + (st_)*32768; \
        int k0 = (kc) * 64; \
        _Pragma("unroll") \
        for (int qq = 0; qq < 8; qq++) { \
            int idx = qq*256 + tid; \
            int sub = idx >> 10; \
            int r = (idx >> 3) & 127; \
            int c = idx & 7; \
            const f16* gp = (sub == 0) ? A : B; \
            size_t rowoff = (sub == 0) ? ((size_t)(iBase + r) * K) : ((size_t)(jBase + r) * K); \
            uint32_t sa = stB + sub*16384 + SW128(r*128 + c*16); \
            cp_async16(sa, gp + rowoff + k0 + c*8); \
        } \
        cp_commit(); \
    } while (0)

    float acc[2][8][4];
    #pragma unroll
    for (int a = 0; a < 2; a++)
        #pragma unroll
        for (int bq_ = 0; bq_ < 8; bq_++)
            #pragma unroll
            for (int cq = 0; cq < 4; cq++) acc[a][bq_][cq] = 0.f;

    const int aRowOff   = lane & 15;
    const int aChunkOff = (lane >> 4) & 1;
    const int bRowOff   = (((lane >> 4) & 1) << 3) + (lane & 7);
    const int bChunkOff = (lane >> 3) & 1;

    LOAD_CHUNK1(0, 0);
    for (int kc = 0; kc < KC; kc++) {
        if (kc + 1 < KC) { LOAD_CHUNK1(kc + 1, (kc + 1) & 1); cp_wait1(); }
        else             { cp_wait0(); }
        __syncthreads();
        uint32_t st = sbase + (kc & 1) * 32768;
        #pragma unroll
        for (int ks = 0; ks < 4; ks++) {
            uint32_t ah[2][4];
            #pragma unroll
            for (int mt = 0; mt < 2; mt++) {
                int row = warpM*32 + mt*16 + aRowOff;
                ldm_x4(ah[mt], st + SW128((uint32_t)(row*128 + (2*ks + aChunkOff)*16)));
            }
            uint32_t bh[8][2];
            #pragma unroll
            for (int np = 0; np < 4; np++) {
                int row = warpN*64 + np*16 + bRowOff;
                uint32_t r4[4];
                ldm_x4(r4, st + 16384 + SW128((uint32_t)(row*128 + (2*ks + bChunkOff)*16)));
                bh[np*2][0] = r4[0]; bh[np*2][1] = r4[1];
                bh[np*2+1][0] = r4[2]; bh[np*2+1][1] = r4[3];
            }
            #pragma unroll
            for (int mt = 0; mt < 2; mt++)
                #pragma unroll
                for (int nt = 0; nt < 8; nt++)
                    mma16816(acc[mt][nt], ah[mt], bh[nt][0], bh[nt][1]);
        }
        __syncthreads();
    }
    #undef LOAD_CHUNK1

    const int g = lane >> 2, t = lane & 3;
    #pragma unroll
    for (int mt = 0; mt < 2; mt++) {
        int r0 = iBase + warpM*32 + mt*16 + g;
        int r1 = r0 + 8;
        float bi0 = biasI[r0];
        float bi1 = biasI[r1];
        #pragma unroll
        for (int nt = 0; nt < 8; nt++) {
            int j = jBase + warpN*64 + nt*8 + 2*t;
            float v00 = acc[mt][nt][0] + bi0;
            float v01 = acc[mt][nt][1] + bi0;
            float v10 = acc[mt][nt][2] + bi1;
            float v11 = acc[mt][nt][3] + bi1;
            const float* rp = resid + (size_t)z*sR;
            v00 = (v00 + rp[(size_t)r0*ldo + j  ]) * oscale;
            v01 = (v01 + rp[(size_t)r0*ldo + j+1]) * oscale;
            v10 = (v10 + rp[(size_t)r1*ldo + j  ]) * oscale;
            v11 = (v11 + rp[(size_t)r1*ldo + j+1]) * oscale;
            float* op = outF + (size_t)z*sO;
            *(float2*)(op + (size_t)r0*ldo + j) = make_float2(v00, v01);
            *(float2*)(op + (size_t)r1*ldo + j) = make_float2(v10, v11);
        }
    }
}

// ---------------- flash (R14): 3-stage KV ring, one barrier/iter ----------------
// SMEM: QHI @0 32KB (Q ch 128..255); stage s @32768 + s*65536: K 32KB then V 32KB.
__global__ void __launch_bounds__(256, 1) flash_kernel() {
    extern __shared__ char smem[];
    const int tid = threadIdx.x, w = tid >> 5, lane = tid & 31;
    const int z = blockIdx.y;
    const int qbase = blockIdx.x * QT;
    const f16* qp = g_q + (size_t)z*HWN*CC;
    const f16* kp = g_k + (size_t)z*HWN*CC;
    const f16* vp = g_v + (size_t)z*CC*HWN;

    const uint32_t sb = smem_u32(smem);
    const uint32_t QHI = 0, STG = 32768, SSTRIDE = 65536, VOFF = 32768;

    #pragma unroll
    for (int q8 = 0; q8 < 8; q8++) {
        int idx = q8*256 + tid;
        int c = idx >> 10, r = (idx >> 3) & 127, b = idx & 7;
        cp_async16(sb + STG + c*16384 + SW128(r*128 + b*16),
                   qp + (size_t)(qbase + r)*CC + c*64 + b*8);
        cp_async16(sb + QHI + c*16384 + SW128(r*128 + b*16),
                   qp + (size_t)(qbase + r)*CC + 128 + c*64 + b*8);
    }
    cp_commit();

    const int aRowOff   = lane & 15;
    const int aChunkOff = (lane >> 4) & 1;
    const int bRowOff   = (((lane >> 4) & 1) << 3) + (lane & 7);
    const int bChunkOff = (lane >> 3) & 1;

    cp_wait0();
    __syncthreads();
    uint32_t qf[8][4];
    #pragma unroll
    for (int ks = 0; ks < 8; ks++) {
        const int cq = ks >> 2, kk = ks & 3;
        ldm_x4(qf[ks], sb + STG + cq*16384 +
                   SW128((uint32_t)((w*16 + aRowOff)*128 + (2*kk + aChunkOff)*16)));
    }
    __syncthreads();

    #define LOAD_KV(it_, s_) do { \
        int key0 = (it_) * KT; \
        uint32_t stb = sb + STG + (s_)*SSTRIDE; \
        _Pragma("unroll") \
        for (int q8 = 0; q8 < 8; q8++) { \
            int idx = q8*256 + tid; \
            int c = idx >> 9, r = (idx >> 3) & 63, b = idx & 7; \
            cp_async16(stb + c*8192 + SW128(r*128 + b*16), \
                       kp + (size_t)(key0 + r)*CC + c*64 + b*8); \
        } \
        _Pragma("unroll") \
        for (int q8 = 0; q8 < 8; q8++) { \
            int idx = q8*256 + tid; \
            int r = (idx >> 3) & 255, b = idx & 7; \
            cp_async16(stb + VOFF + SW128(r*128 + b*16), \
                       vp + (size_t)r*HWN + key0 + b*8); \
        } \
        cp_commit(); \
    } while (0)

    LOAD_KV(0, 0);
    LOAD_KV(1, 1);

    float accO[32][4];
    #pragma unroll
    for (int nt = 0; nt < 32; nt++)
        #pragma unroll
        for (int c = 0; c < 4; c++) accO[nt][c] = 0.f;

    float l0 = 0.f, l1 = 0.f;

    int s_cur = 0, s_nxt2 = 2;
    for (int it = 0; it < NIT; it++) {
        cp_wait1();
        __syncthreads();

        if (it + 2 < NIT) LOAD_KV(it + 2, s_nxt2);

        const uint32_t kst = sb + STG + s_cur*SSTRIDE;
        const uint32_t vst = kst + VOFF;

        float sacc[8][4];
        #pragma unroll
        for (int nt = 0; nt < 8; nt++)
            #pragma unroll
            for (int c = 0; c < 4; c++) sacc[nt][c] = 0.f;
        #pragma unroll
        for (int ks = 0; ks < 16; ks++) {
            const int kk = ks & 3;
            uint32_t aq[4];
            if (ks < 8) {
                aq[0] = qf[ks][0]; aq[1] = qf[ks][1]; aq[2] = qf[ks][2]; aq[3] = qf[ks][3];
            } else {
                const int cql = (ks >> 2) - 2;
                ldm_x4(aq, sb + QHI + cql*16384 +
                           SW128((uint32_t)((w*16 + aRowOff)*128 + (2*kk + aChunkOff)*16)));
            }
            const int cq = ks >> 2;
            uint32_t bk[8][2];
            #pragma unroll
            for (int np = 0; np < 4; np++) {
                uint32_t r4[4];
                ldm_x4(r4, kst + cq*8192 +
                           SW128((uint32_t)((np*16 + bRowOff)*128 + (2*kk + bChunkOff)*16)));
                bk[np*2][0] = r4[0]; bk[np*2][1] = r4[1];
                bk[np*2+1][0] = r4[2]; bk[np*2+1][1] = r4[3];
            }
            #pragma unroll
            for (int nt = 0; nt < 8; nt++) mma16816(sacc[nt], aq, bk[nt][0], bk[nt][1]);
        }

        #pragma unroll
        for (int kk = 0; kk < 4; kk++) {
            const int n0 = 2*kk, n1 = 2*kk + 1;
            sacc[n0][0] = ex2(sacc[n0][0]); sacc[n0][1] = ex2(sacc[n0][1]);
            sacc[n0][2] = ex2(sacc[n0][2]); sacc[n0][3] = ex2(sacc[n0][3]);
            sacc[n1][0] = ex2(sacc[n1][0]); sacc[n1][1] = ex2(sacc[n1][1]);
            sacc[n1][2] = ex2(sacc[n1][2]); sacc[n1][3] = ex2(sacc[n1][3]);
            l0 += sacc[n0][0] + sacc[n0][1] + sacc[n1][0] + sacc[n1][1];
            l1 += sacc[n0][2] + sacc[n0][3] + sacc[n1][2] + sacc[n1][3];
            uint32_t aP[4];
            aP[0] = packh2(sacc[n0][0], sacc[n0][1]);
            aP[1] = packh2(sacc[n0][2], sacc[n0][3]);
            aP[2] = packh2(sacc[n1][0], sacc[n1][1]);
            aP[3] = packh2(sacc[n1][2], sacc[n1][3]);
            #pragma unroll
            for (int np = 0; np < 16; np++) {
                uint32_t r4[4];
                ldm_x4(r4, vst + SW128((uint32_t)((np*16 + bRowOff)*128 + (2*kk + bChunkOff)*16)));
                mma16816(accO[np*2],   aP, r4[0], r4[1]);
                mma16816(accO[np*2+1], aP, r4[2], r4[3]);
            }
        }

        s_cur  = (s_cur  == 2) ? 0 : s_cur + 1;
        s_nxt2 = (s_nxt2 == 2) ? 0 : s_nxt2 + 1;
    }
    #undef LOAD_KV

    #pragma unroll
    for (int d = 1; d < 4; d <<= 1) {
        l0 += __shfl_xor_sync(0xffffffffu, l0, d);
        l1 += __shfl_xor_sync(0xffffffffu, l1, d);
    }
    const int g = lane >> 2, t = lane & 3;
    const float inv0 = 1.0f / l0, inv1 = 1.0f / l1;
    f16* oh = g_oT + (size_t)z*HWN*CC;
    const size_t r0b = (size_t)(qbase + w*16 + g) * CC;
    const size_t r1b = r0b + 8*CC;
    #pragma unroll
    for (int nt = 0; nt < 32; nt++) {
        int col = nt*8 + 2*t;
        *(uint32_t*)(oh + r0b + col) = packh2(accO[nt][0]*inv0, accO[nt][1]*inv0);
        *(uint32_t*)(oh + r1b + col) = packh2(accO[nt][2]*inv1, accO[nt][3]*inv1);
    }
}

// ---------------- launch ----------------
extern "C" void kernel_launch(void* const* d_in, const int* in_sizes, int n_in,
                              void* d_out, int out_size) {
    const float* x    = (const float*)d_in[0];
    const float* gn_w = (const float*)d_in[1];
    const float* gn_b = (const float*)d_in[2];
    const float* Wq   = (const float*)d_in[3];
    const float* bq   = (const float*)d_in[4];
    const float* Wk   = (const float*)d_in[5];
    const float* bk   = (const float*)d_in[6];
    const float* Wv   = (const float*)d_in[7];
    const float* bv   = (const float*)d_in[8];
    const float* Wp   = (const float*)d_in[9];
    const float* bp   = (const float*)d_in[10];
    float* out = (float*)d_out;

    const int SMEMGN  = 8*HWN*4;           // 128KB
    const int SMEMQK  = 65536 + 2*16384;   // 96KB, 2 CTAs/SM
    const int SMEM1   = 2 * 32768;
    const int SMEMFA  = 32768 + 3*65536;   // 229376
    cudaFuncSetAttribute(gn_kernel, cudaFuncAttributeMaxDynamicSharedMemorySize, SMEMGN);
    cudaFuncSetAttribute(qk_kernel, cudaFuncAttributeMaxDynamicSharedMemorySize, SMEMQK);
    cudaFuncSetAttribute(mma_gemm1h, cudaFuncAttributeMaxDynamicSharedMemorySize, SMEM1);
    cudaFuncSetAttribute(mma_gemm1f, cudaFuncAttributeMaxDynamicSharedMemorySize, SMEM1);
    cudaFuncSetAttribute(flash_kernel, cudaFuncAttributeMaxDynamicSharedMemorySize, SMEMFA);

    f16 *wT, *hT, *vv, *oT;
    cudaGetSymbolAddress((void**)&wT, g_wT);
    cudaGetSymbolAddress((void**)&hT, g_hT);
    cudaGetSymbolAddress((void**)&vv, g_v);
    cudaGetSymbolAddress((void**)&oT, g_oT);

    const size_t sNC = (size_t)HWN*CC;
    const float invsqrt2 = 0.70710678118654752f;

    gn_kernel<<<BB*32, 256, SMEMGN>>>(x, gn_w, gn_b);
    wprep_kernel<<<dim3(CC, 4), CC>>>(Wq, Wk, Wv, Wp);

    // q/k: [n,d] coalesced, fused A-resident
    qk_kernel<<<dim3(2, 32, BB), 256, SMEMQK>>>(bq, bk);

    // v[c,m] = WvT . hT + bv[c] — transposed orientation, coalesced stores
    mma_gemm1h<<<dim3(32, 2, BB), 256, SMEM1>>>(
        wT + 2*CC*CC, hT, sNC, CC, vv, HWN, sNC, bv);

    flash_kernel<<<dim3(HWN/QT, BB), 256, SMEMFA>>>();

    // out[d2,n] = (Wp . oT + bp[d2] + x) / sqrt(2)
    mma_gemm1f<<<dim3(32, 2, BB), 256, SMEM1>>>(
        wT + 3*CC*CC, oT, sNC, CC,
        out, HWN, sNC, bp, x, sNC, invsqrt2);
}

// round 17
// speedup vs baseline: 1.0119x; 1.0119x over previous
#include <cuda_runtime.h>
#include <cuda_fp16.h>
#include <stdint.h>
#include <math.h>

#define BB 4
#define CC 256
#define HWN 4096
#define QT 128
#define KT 64
#define NIT (HWN/KT)
#define SW128(x) ((x) ^ (((x) >> 3) & 0x70))

using f16 = __half;

// ---------------- scratch (device globals; no allocation allowed) ----------------
__device__ f16 g_hT[(size_t)BB*HWN*CC];     // groupnorm out, [n,c] fp16
__device__ f16 g_wT[4*CC*CC];               // WT[d,c] (q,k,v,p consecutive)
__device__ f16 g_q[(size_t)BB*HWN*CC];      // qT[n,d], pre-scaled by log2e/16
__device__ f16 g_k[(size_t)BB*HWN*CC];      // kT[n,d]
__device__ f16 g_v[(size_t)BB*CC*HWN];      // v[c,m]
__device__ f16 g_oT[(size_t)BB*HWN*CC];     // attention out, fp16

// ---------------- helpers ----------------
__device__ __forceinline__ uint32_t smem_u32(const void* p) {
    uint32_t a;
    asm("{ .reg .u64 t; cvta.to.shared.u64 t, %1; cvt.u32.u64 %0, t; }" : "=r"(a) : "l"(p));
    return a;
}
__device__ __forceinline__ uint32_t packh2(float lo, float hi) {
    uint32_t u;
    asm("cvt.rn.f16x2.f32 %0, %2, %1;" : "=r"(u) : "f"(lo), "f"(hi));
    return u;
}
__device__ __forceinline__ uint32_t h2ex2(uint32_t x) {
    uint32_t r;
    asm("ex2.approx.f16x2 %0, %1;" : "=r"(r) : "r"(x));
    return r;
}
__device__ __forceinline__ void cp_async16(uint32_t saddr, const void* g) {
    asm volatile("cp.async.cg.shared.global [%0], [%1], 16;" :: "r"(saddr), "l"(g) : "memory");
}
__device__ __forceinline__ void cp_commit() { asm volatile("cp.async.commit_group;" ::: "memory"); }
__device__ __forceinline__ void cp_wait1()  { asm volatile("cp.async.wait_group 1;" ::: "memory"); }
__device__ __forceinline__ void cp_wait0()  { asm volatile("cp.async.wait_group 0;" ::: "memory"); }

__device__ __forceinline__ void ldm_x4(uint32_t (&r)[4], uint32_t a) {
    asm volatile("ldmatrix.sync.aligned.m8n8.x4.shared.b16 {%0,%1,%2,%3}, [%4];"
        : "=r"(r[0]), "=r"(r[1]), "=r"(r[2]), "=r"(r[3]) : "r"(a));
}
__device__ __forceinline__ void mma16816(float (&d)[4], const uint32_t (&a)[4],
                                         uint32_t b0, uint32_t b1) {
    asm volatile(
        "mma.sync.aligned.m16n8k16.row.col.f32.f16.f16.f32 "
        "{%0,%1,%2,%3},{%4,%5,%6,%7},{%8,%9},{%0,%1,%2,%3};"
        : "+f"(d[0]), "+f"(d[1]), "+f"(d[2]), "+f"(d[3])
        : "r"(a[0]), "r"(a[1]), "r"(a[2]), "r"(a[3]), "r"(b0), "r"(b1));
}

// ---------------- GroupNorm (single gmem read via SMEM slab) ----------------
__global__ void __launch_bounds__(256, 1) gn_kernel(
    const float* __restrict__ x, const float* __restrict__ w, const float* __restrict__ b) {
    extern __shared__ float xs[];   // 8 * 4096 floats = 128KB
    int batch = blockIdx.x >> 5, g = blockIdx.x & 31;
    const float* xp = x + ((size_t)batch*CC + g*8) * HWN;
    int tid = threadIdx.x;
    float s = 0.f, ss = 0.f;
    for (int i = tid; i < 8*HWN; i += 256) {
        float v = xp[i];
        xs[i] = v;
        s += v; ss += v*v;
    }
    __shared__ float rs[256], rss[256];
    rs[tid] = s; rss[tid] = ss;
    __syncthreads();
    for (int st = 128; st > 0; st >>= 1) {
        if (tid < st) { rs[tid] += rs[tid+st]; rss[tid] += rss[tid+st]; }
        __syncthreads();
    }
    float mean = rs[0] * (1.f/32768.f);
    float var  = rss[0] * (1.f/32768.f) - mean*mean;
    float rstd = rsqrtf(var + 1e-5f);
    float ws[8], bs[8];
    #pragma unroll
    for (int c = 0; c < 8; c++) { ws[c] = w[g*8+c]*rstd; bs[c] = b[g*8+c]; }
    f16* oh = g_hT + (size_t)batch*HWN*CC + g*8;
    for (int n = tid; n < HWN; n += 256) {
        union { f16 v[8]; uint4 u; } hh;
        #pragma unroll
        for (int c = 0; c < 8; c++) {
            float v = (xs[c*HWN + n] - mean)*ws[c] + bs[c];
            hh.v[c] = __float2half(v);
        }
        *(uint4*)(oh + (size_t)n*CC) = hh.u;
    }
}

// ---------------- weight transpose: W[c,d] -> WT[d,c] fp16 ----------------
__global__ void wprep_kernel(const float* __restrict__ Wq, const float* __restrict__ Wk,
                             const float* __restrict__ Wv, const float* __restrict__ Wp) {
    const float* W = (blockIdx.y == 0) ? Wq : (blockIdx.y == 1) ? Wk : (blockIdx.y == 2) ? Wv : Wp;
    int d = blockIdx.x, c = threadIdx.x;
    g_wT[(size_t)blockIdx.y*CC*CC + (size_t)d*CC + c] = __float2half(W[(size_t)c*CC + d]);
}

// ---------------- fused QK: A (hT tile) resident, stream q,k weight B-tiles ----------------
__global__ void __launch_bounds__(256, 2) qk_kernel(
    const float* __restrict__ bq, const float* __restrict__ bk)
{
    extern __shared__ char smem[];
    const int tid = threadIdx.x;
    const int wid = tid >> 5, lane = tid & 31;
    const int warpM = wid & 3, warpN = wid >> 2;
    const int iBase = blockIdx.y * 128;
    const int jBase = blockIdx.x * 128;
    const int z = blockIdx.z;
    const f16* Ap = g_hT + (size_t)z*HWN*CC;

    const uint32_t sb = smem_u32(smem);
    const uint32_t BOFF = 65536;
    const float SCALE_Q = 0.0625f * 1.44269504088896f;

    #pragma unroll
    for (int q16 = 0; q16 < 16; q16++) {
        int idx = q16*256 + tid;
        int c = idx >> 10, r = (idx >> 3) & 127, b = idx & 7;
        cp_async16(sb + c*16384 + SW128(r*128 + b*16),
                   Ap + (size_t)(iBase + r)*CC + c*64 + b*8);
    }
    #define LOAD_B(m_, s_) do { \
        int o_ = (m_) >> 2, kc_ = (m_) & 3; \
        const f16* src = g_wT + (size_t)o_*CC*CC; \
        _Pragma("unroll") \
        for (int q4 = 0; q4 < 4; q4++) { \
            int idx = q4*256 + tid; \
            int r = (idx >> 3) & 127, b = idx & 7; \
            cp_async16(sb + BOFF + (s_)*16384 + SW128(r*128 + b*16), \
                       src + (size_t)(jBase + r)*CC + kc_*64 + b*8); \
        } \
    } while (0)

    LOAD_B(0, 0);
    cp_commit();

    const int aRowOff   = lane & 15;
    const int aChunkOff = (lane >> 4) & 1;
    const int bRowOff   = (((lane >> 4) & 1) << 3) + (lane & 7);
    const int bChunkOff = (lane >> 3) & 1;
    const int g = lane >> 2, t = lane & 3;

    float acc[2][8][4];

    for (int m = 0; m < 8; m++) {
        const int kc = m & 3, o = m >> 2;
        if (kc == 0) {
            #pragma unroll
            for (int a = 0; a < 2; a++)
                #pragma unroll
                for (int bq_ = 0; bq_ < 8; bq_++)
                    #pragma unroll
                    for (int cq = 0; cq < 4; cq++) acc[a][bq_][cq] = 0.f;
        }
        if (m > 0) __syncthreads();
        if (m + 1 < 8) { LOAD_B(m + 1, (m + 1) & 1); cp_commit(); cp_wait1(); }
        else           { cp_wait0(); }
        __syncthreads();

        const uint32_t ast = sb + kc*16384;
        const uint32_t bst = sb + BOFF + (m & 1)*16384;
        #pragma unroll
        for (int ks = 0; ks < 4; ks++) {
            uint32_t ah[2][4];
            #pragma unroll
            for (int mt = 0; mt < 2; mt++) {
                int row = warpM*32 + mt*16 + aRowOff;
                ldm_x4(ah[mt], ast + SW128((uint32_t)(row*128 + (2*ks + aChunkOff)*16)));
            }
            uint32_t bh[8][2];
            #pragma unroll
            for (int np = 0; np < 4; np++) {
                int row = warpN*64 + np*16 + bRowOff;
                uint32_t r4[4];
                ldm_x4(r4, bst + SW128((uint32_t)(row*128 + (2*ks + bChunkOff)*16)));
                bh[np*2][0] = r4[0]; bh[np*2][1] = r4[1];
                bh[np*2+1][0] = r4[2]; bh[np*2+1][1] = r4[3];
            }
            #pragma unroll
            for (int mt = 0; mt < 2; mt++)
                #pragma unroll
                for (int nt = 0; nt < 8; nt++)
                    mma16816(acc[mt][nt], ah[mt], bh[nt][0], bh[nt][1]);
        }

        if (kc == 3) {
            const float* bias = (o == 0) ? bq : bk;
            f16* qkp = ((o == 0) ? g_q : g_k) + (size_t)z*HWN*CC;
            const float sc = (o == 0) ? SCALE_Q : 1.0f;
            #pragma unroll
            for (int mt = 0; mt < 2; mt++) {
                int r0 = iBase + warpM*32 + mt*16 + g;
                int r1 = r0 + 8;
                #pragma unroll
                for (int nt = 0; nt < 8; nt++) {
                    int j = jBase + warpN*64 + nt*8 + 2*t;
                    float bj0 = bias[j], bj1 = bias[j+1];
                    *(uint32_t*)(qkp + (size_t)r0*CC + j) =
                        packh2((acc[mt][nt][0] + bj0)*sc, (acc[mt][nt][1] + bj1)*sc);
                    *(uint32_t*)(qkp + (size_t)r1*CC + j) =
                        packh2((acc[mt][nt][2] + bj0)*sc, (acc[mt][nt][3] + bj1)*sc);
                }
            }
        }
    }
    #undef LOAD_B
}

// ---------------- 1-term fp16 GEMM (NT), fp16 out + row bias — used for V ----------------
__global__ void __launch_bounds__(256, 2) mma_gemm1h(
    const f16* __restrict__ A,
    const f16* __restrict__ B, size_t sB,
    int K,
    f16* __restrict__ outH, int ldo, size_t sO,
    const float* __restrict__ biasI)
{
    extern __shared__ char smem[];
    const int tid = threadIdx.x;
    const int wid = tid >> 5, lane = tid & 31;
    const int warpM = wid & 3, warpN = wid >> 2;
    const int iBase = blockIdx.y * 128;
    const int jBase = blockIdx.x * 128;
    const int z = blockIdx.z;
    B += (size_t)z * sB;

    const uint32_t sbase = smem_u32(smem);
    const int KC = K >> 6;

    #define LOAD_CHUNK1(kc, st_) do { \
        uint32_t stB = sbase + (st_)*32768; \
        int k0 = (kc) * 64; \
        _Pragma("unroll") \
        for (int qq = 0; qq < 8; qq++) { \
            int idx = qq*256 + tid; \
            int sub = idx >> 10; \
            int r = (idx >> 3) & 127; \
            int c = idx & 7; \
            const f16* gp = (sub == 0) ? A : B; \
            size_t rowoff = (sub == 0) ? ((size_t)(iBase + r) * K) : ((size_t)(jBase + r) * K); \
            uint32_t sa = stB + sub*16384 + SW128(r*128 + c*16); \
            cp_async16(sa, gp + rowoff + k0 + c*8); \
        } \
        cp_commit(); \
    } while (0)

    float acc[2][8][4];
    #pragma unroll
    for (int a = 0; a < 2; a++)
        #pragma unroll
        for (int bq_ = 0; bq_ < 8; bq_++)
            #pragma unroll
            for (int cq = 0; cq < 4; cq++) acc[a][bq_][cq] = 0.f;

    const int aRowOff   = lane & 15;
    const int aChunkOff = (lane >> 4) & 1;
    const int bRowOff   = (((lane >> 4) & 1) << 3) + (lane & 7);
    const int bChunkOff = (lane >> 3) & 1;

    LOAD_CHUNK1(0, 0);
    for (int kc = 0; kc < KC; kc++) {
        if (kc + 1 < KC) { LOAD_CHUNK1(kc + 1, (kc + 1) & 1); cp_wait1(); }
        else             { cp_wait0(); }
        __syncthreads();
        uint32_t st = sbase + (kc & 1) * 32768;
        #pragma unroll
        for (int ks = 0; ks < 4; ks++) {
            uint32_t ah[2][4];
            #pragma unroll
            for (int mt = 0; mt < 2; mt++) {
                int row = warpM*32 + mt*16 + aRowOff;
                ldm_x4(ah[mt], st + SW128((uint32_t)(row*128 + (2*ks + aChunkOff)*16)));
            }
            uint32_t bh[8][2];
            #pragma unroll
            for (int np = 0; np < 4; np++) {
                int row = warpN*64 + np*16 + bRowOff;
                uint32_t r4[4];
                ldm_x4(r4, st + 16384 + SW128((uint32_t)(row*128 + (2*ks + bChunkOff)*16)));
                bh[np*2][0] = r4[0]; bh[np*2][1] = r4[1];
                bh[np*2+1][0] = r4[2]; bh[np*2+1][1] = r4[3];
            }
            #pragma unroll
            for (int mt = 0; mt < 2; mt++)
                #pragma unroll
                for (int nt = 0; nt < 8; nt++)
                    mma16816(acc[mt][nt], ah[mt], bh[nt][0], bh[nt][1]);
        }
        __syncthreads();
    }
    #undef LOAD_CHUNK1

    const int g = lane >> 2, t = lane & 3;
    #pragma unroll
    for (int mt = 0; mt < 2; mt++) {
        int r0 = iBase + warpM*32 + mt*16 + g;
        int r1 = r0 + 8;
        float bi0 = biasI[r0];
        float bi1 = biasI[r1];
        #pragma unroll
        for (int nt = 0; nt < 8; nt++) {
            int j = jBase + warpN*64 + nt*8 + 2*t;
            f16* op = outH + (size_t)z*sO;
            *(uint32_t*)(op + (size_t)r0*ldo + j) = packh2(acc[mt][nt][0] + bi0, acc[mt][nt][1] + bi0);
            *(uint32_t*)(op + (size_t)r1*ldo + j) = packh2(acc[mt][nt][2] + bi1, acc[mt][nt][3] + bi1);
        }
    }
}

// ---------------- 1-term fp16 GEMM (NT), fp32 out + residual — final projection ----------------
__global__ void __launch_bounds__(256, 2) mma_gemm1f(
    const f16* __restrict__ A,
    const f16* __restrict__ B, size_t sB,
    int K,
    float* __restrict__ outF, int ldo, size_t sO,
    const float* __restrict__ biasI,
    const float* __restrict__ resid, size_t sR, float oscale)
{
    extern __shared__ char smem[];
    const int tid = threadIdx.x;
    const int wid = tid >> 5, lane = tid & 31;
    const int warpM = wid & 3, warpN = wid >> 2;
    const int iBase = blockIdx.y * 128;
    const int jBase = blockIdx.x * 128;
    const int z = blockIdx.z;
    B += (size_t)z * sB;

    const uint32_t sbase = smem_u32(smem);
    const int KC = K >> 6;

    #define LOAD_CHUNK1(kc, st_) do { \
        uint32_t stB = sbase + (st_)*32768; \
        int k0 = (kc) * 64; \
        _Pragma("unroll") \
        for (int qq = 0; qq < 8; qq++) { \
            int idx = qq*256 + tid; \
            int sub = idx >> 10; \
            int r = (idx >> 3) & 127; \
            int c = idx & 7; \
            const f16* gp = (sub == 0) ? A : B; \
            size_t rowoff = (sub == 0) ? ((size_t)(iBase + r) * K) : ((size_t)(jBase + r) * K); \
            uint32_t sa = stB + sub*16384 + SW128(r*128 + c*16); \
            cp_async16(sa, gp + rowoff + k0 + c*8); \
        } \
        cp_commit(); \
    } while (0)

    float acc[2][8][4];
    #pragma unroll
    for (int a = 0; a < 2; a++)
        #pragma unroll
        for (int bq_ = 0; bq_ < 8; bq_++)
            #pragma unroll
            for (int cq = 0; cq < 4; cq++) acc[a][bq_][cq] = 0.f;

    const int aRowOff   = lane & 15;
    const int aChunkOff = (lane >> 4) & 1;
    const int bRowOff   = (((lane >> 4) & 1) << 3) + (lane & 7);
    const int bChunkOff = (lane >> 3) & 1;

    LOAD_CHUNK1(0, 0);
    for (int kc = 0; kc < KC; kc++) {
        if (kc + 1 < KC) { LOAD_CHUNK1(kc + 1, (kc + 1) & 1); cp_wait1(); }
        else             { cp_wait0(); }
        __syncthreads();
        uint32_t st = sbase + (kc & 1) * 32768;
        #pragma unroll
        for (int ks = 0; ks < 4; ks++) {
            uint32_t ah[2][4];
            #pragma unroll
            for (int mt = 0; mt < 2; mt++) {
                int row = warpM*32 + mt*16 + aRowOff;
                ldm_x4(ah[mt], st + SW128((uint32_t)(row*128 + (2*ks + aChunkOff)*16)));
            }
            uint32_t bh[8][2];
            #pragma unroll
            for (int np = 0; np < 4; np++) {
                int row = warpN*64 + np*16 + bRowOff;
                uint32_t r4[4];
                ldm_x4(r4, st + 16384 + SW128((uint32_t)(row*128 + (2*ks + bChunkOff)*16)));
                bh[np*2][0] = r4[0]; bh[np*2][1] = r4[1];
                bh[np*2+1][0] = r4[2]; bh[np*2+1][1] = r4[3];
            }
            #pragma unroll
            for (int mt = 0; mt < 2; mt++)
                #pragma unroll
                for (int nt = 0; nt < 8; nt++)
                    mma16816(acc[mt][nt], ah[mt], bh[nt][0], bh[nt][1]);
        }
        __syncthreads();
    }
    #undef LOAD_CHUNK1

    const int g = lane >> 2, t = lane & 3;
    #pragma unroll
    for (int mt = 0; mt < 2; mt++) {
        int r0 = iBase + warpM*32 + mt*16 + g;
        int r1 = r0 + 8;
        float bi0 = biasI[r0];
        float bi1 = biasI[r1];
        #pragma unroll
        for (int nt = 0; nt < 8; nt++) {
            int j = jBase + warpN*64 + nt*8 + 2*t;
            float v00 = acc[mt][nt][0] + bi0;
            float v01 = acc[mt][nt][1] + bi0;
            float v10 = acc[mt][nt][2] + bi1;
            float v11 = acc[mt][nt][3] + bi1;
            const float* rp = resid + (size_t)z*sR;
            v00 = (v00 + rp[(size_t)r0*ldo + j  ]) * oscale;
            v01 = (v01 + rp[(size_t)r0*ldo + j+1]) * oscale;
            v10 = (v10 + rp[(size_t)r1*ldo + j  ]) * oscale;
            v11 = (v11 + rp[(size_t)r1*ldo + j+1]) * oscale;
            float* op = outF + (size_t)z*sO;
            *(float2*)(op + (size_t)r0*ldo + j) = make_float2(v00, v01);
            *(float2*)(op + (size_t)r1*ldo + j) = make_float2(v10, v11);
        }
    }
}

// ---------------- flash v8: f16x2 exp + MMA row-sums; 3-stage KV ring ----------------
// SMEM: QHI @0 32KB (Q ch 128..255); stage s @32768 + s*65536: K 32KB then V 32KB.
__global__ void __launch_bounds__(256, 1) flash_kernel() {
    extern __shared__ char smem[];
    const int tid = threadIdx.x, w = tid >> 5, lane = tid & 31;
    const int z = blockIdx.y;
    const int qbase = blockIdx.x * QT;
    const f16* qp = g_q + (size_t)z*HWN*CC;
    const f16* kp = g_k + (size_t)z*HWN*CC;
    const f16* vp = g_v + (size_t)z*CC*HWN;

    const uint32_t sb = smem_u32(smem);
    const uint32_t QHI = 0, STG = 32768, SSTRIDE = 65536, VOFF = 32768;
    const uint32_t ONES = 0x3C003C00u;   // fp16x2 {1.0, 1.0}

    #pragma unroll
    for (int q8 = 0; q8 < 8; q8++) {
        int idx = q8*256 + tid;
        int c = idx >> 10, r = (idx >> 3) & 127, b = idx & 7;
        cp_async16(sb + STG + c*16384 + SW128(r*128 + b*16),
                   qp + (size_t)(qbase + r)*CC + c*64 + b*8);
        cp_async16(sb + QHI + c*16384 + SW128(r*128 + b*16),
                   qp + (size_t)(qbase + r)*CC + 128 + c*64 + b*8);
    }
    cp_commit();

    const int aRowOff   = lane & 15;
    const int aChunkOff = (lane >> 4) & 1;
    const int bRowOff   = (((lane >> 4) & 1) << 3) + (lane & 7);
    const int bChunkOff = (lane >> 3) & 1;

    cp_wait0();
    __syncthreads();
    uint32_t qf[8][4];
    #pragma unroll
    for (int ks = 0; ks < 8; ks++) {
        const int cq = ks >> 2, kk = ks & 3;
        ldm_x4(qf[ks], sb + STG + cq*16384 +
                   SW128((uint32_t)((w*16 + aRowOff)*128 + (2*kk + aChunkOff)*16)));
    }
    __syncthreads();

    #define LOAD_KV(it_, s_) do { \
        int key0 = (it_) * KT; \
        uint32_t stb = sb + STG + (s_)*SSTRIDE; \
        _Pragma("unroll") \
        for (int q8 = 0; q8 < 8; q8++) { \
            int idx = q8*256 + tid; \
            int c = idx >> 9, r = (idx >> 3) & 63, b = idx & 7; \
            cp_async16(stb + c*8192 + SW128(r*128 + b*16), \
                       kp + (size_t)(key0 + r)*CC + c*64 + b*8); \
        } \
        _Pragma("unroll") \
        for (int q8 = 0; q8 < 8; q8++) { \
            int idx = q8*256 + tid; \
            int r = (idx >> 3) & 255, b = idx & 7; \
            cp_async16(stb + VOFF + SW128(r*128 + b*16), \
                       vp + (size_t)r*HWN + key0 + b*8); \
        } \
        cp_commit(); \
    } while (0)

    LOAD_KV(0, 0);
    LOAD_KV(1, 1);

    float accO[32][4];
    #pragma unroll
    for (int nt = 0; nt < 32; nt++)
        #pragma unroll
        for (int c = 0; c < 4; c++) accO[nt][c] = 0.f;
    float accL[4] = {0.f, 0.f, 0.f, 0.f};   // row sums via ones-MMA

    int s_cur = 0, s_nxt2 = 2;
    for (int it = 0; it < NIT; it++) {
        cp_wait1();
        __syncthreads();

        if (it + 2 < NIT) LOAD_KV(it + 2, s_nxt2);

        const uint32_t kst = sb + STG + s_cur*SSTRIDE;
        const uint32_t vst = kst + VOFF;

        float sacc[8][4];
        #pragma unroll
        for (int nt = 0; nt < 8; nt++)
            #pragma unroll
            for (int c = 0; c < 4; c++) sacc[nt][c] = 0.f;
        #pragma unroll
        for (int ks = 0; ks < 16; ks++) {
            const int kk = ks & 3;
            uint32_t aq[4];
            if (ks < 8) {
                aq[0] = qf[ks][0]; aq[1] = qf[ks][1]; aq[2] = qf[ks][2]; aq[3] = qf[ks][3];
            } else {
                const int cql = (ks >> 2) - 2;
                ldm_x4(aq, sb + QHI + cql*16384 +
                           SW128((uint32_t)((w*16 + aRowOff)*128 + (2*kk + aChunkOff)*16)));
            }
            const int cq = ks >> 2;
            uint32_t bk[8][2];
            #pragma unroll
            for (int np = 0; np < 4; np++) {
                uint32_t r4[4];
                ldm_x4(r4, kst + cq*8192 +
                           SW128((uint32_t)((np*16 + bRowOff)*128 + (2*kk + bChunkOff)*16)));
                bk[np*2][0] = r4[0]; bk[np*2][1] = r4[1];
                bk[np*2+1][0] = r4[2]; bk[np*2+1][1] = r4[3];
            }
            #pragma unroll
            for (int nt = 0; nt < 8; nt++) mma16816(sacc[nt], aq, bk[nt][0], bk[nt][1]);
        }

        // ---- per 16-key group: pack -> f16x2 exp -> l via ones-MMA -> PV ----
        #pragma unroll
        for (int kk = 0; kk < 4; kk++) {
            const int n0 = 2*kk, n1 = 2*kk + 1;
            uint32_t aP[4];
            aP[0] = h2ex2(packh2(sacc[n0][0], sacc[n0][1]));
            aP[1] = h2ex2(packh2(sacc[n0][2], sacc[n0][3]));
            aP[2] = h2ex2(packh2(sacc[n1][0], sacc[n1][1]));
            aP[3] = h2ex2(packh2(sacc[n1][2], sacc[n1][3]));
            mma16816(accL, aP, ONES, ONES);
            #pragma unroll
            for (int np = 0; np < 16; np++) {
                uint32_t r4[4];
                ldm_x4(r4, vst + SW128((uint32_t)((np*16 + bRowOff)*128 + (2*kk + bChunkOff)*16)));
                mma16816(accO[np*2],   aP, r4[0], r4[1]);
                mma16816(accO[np*2+1], aP, r4[2], r4[3]);
            }
        }

        s_cur  = (s_cur  == 2) ? 0 : s_cur + 1;
        s_nxt2 = (s_nxt2 == 2) ? 0 : s_nxt2 + 1;
    }
    #undef LOAD_KV

    // ---- normalize (accL[0]/accL[2] hold full row sums), store oT fp16 ----
    const int g = lane >> 2, t = lane & 3;
    const float inv0 = 1.0f / accL[0], inv1 = 1.0f / accL[2];
    f16* oh = g_oT + (size_t)z*HWN*CC;
    const size_t r0b = (size_t)(qbase + w*16 + g) * CC;
    const size_t r1b = r0b + 8*CC;
    #pragma unroll
    for (int nt = 0; nt < 32; nt++) {
        int col = nt*8 + 2*t;
        *(uint32_t*)(oh + r0b + col) = packh2(accO[nt][0]*inv0, accO[nt][1]*inv0);
        *(uint32_t*)(oh + r1b + col) = packh2(accO[nt][2]*inv1, accO[nt][3]*inv1);
    }
}

// ---------------- launch ----------------
extern "C" void kernel_launch(void* const* d_in, const int* in_sizes, int n_in,
                              void* d_out, int out_size) {
    const float* x    = (const float*)d_in[0];
    const float* gn_w = (const float*)d_in[1];
    const float* gn_b = (const float*)d_in[2];
    const float* Wq   = (const float*)d_in[3];
    const float* bq   = (const float*)d_in[4];
    const float* Wk   = (const float*)d_in[5];
    const float* bk   = (const float*)d_in[6];
    const float* Wv   = (const float*)d_in[7];
    const float* bv   = (const float*)d_in[8];
    const float* Wp   = (const float*)d_in[9];
    const float* bp   = (const float*)d_in[10];
    float* out = (float*)d_out;

    const int SMEMGN  = 8*HWN*4;
    const int SMEMQK  = 65536 + 2*16384;
    const int SMEM1   = 2 * 32768;
    const int SMEMFA  = 32768 + 3*65536;   // 229376
    cudaFuncSetAttribute(gn_kernel, cudaFuncAttributeMaxDynamicSharedMemorySize, SMEMGN);
    cudaFuncSetAttribute(qk_kernel, cudaFuncAttributeMaxDynamicSharedMemorySize, SMEMQK);
    cudaFuncSetAttribute(mma_gemm1h, cudaFuncAttributeMaxDynamicSharedMemorySize, SMEM1);
    cudaFuncSetAttribute(mma_gemm1f, cudaFuncAttributeMaxDynamicSharedMemorySize, SMEM1);
    cudaFuncSetAttribute(flash_kernel, cudaFuncAttributeMaxDynamicSharedMemorySize, SMEMFA);

    f16 *wT, *hT, *vv, *oT;
    cudaGetSymbolAddress((void**)&wT, g_wT);
    cudaGetSymbolAddress((void**)&hT, g_hT);
    cudaGetSymbolAddress((void**)&vv, g_v);
    cudaGetSymbolAddress((void**)&oT, g_oT);

    const size_t sNC = (size_t)HWN*CC;
    const float invsqrt2 = 0.70710678118654752f;

    gn_kernel<<<BB*32, 256, SMEMGN>>>(x, gn_w, gn_b);
    wprep_kernel<<<dim3(CC, 4), CC>>>(Wq, Wk, Wv, Wp);

    qk_kernel<<<dim3(2, 32, BB), 256, SMEMQK>>>(bq, bk);

    mma_gemm1h<<<dim3(32, 2, BB), 256, SMEM1>>>(
        wT + 2*CC*CC, hT, sNC, CC, vv, HWN, sNC, bv);

    flash_kernel<<<dim3(HWN/QT, BB), 256, SMEMFA>>>();

    mma_gemm1f<<<dim3(32, 2, BB), 256, SMEM1>>>(
        wT + 3*CC*CC, oT, sNC, CC,
        out, HWN, sNC, bp, x, sNC, invsqrt2);
}